// round 7
// baseline (speedup 1.0000x reference)
#include <cuda_runtime.h>

typedef unsigned long long u64;

#define NN 64
#define TT 5
#define VV 64
#define FF 256
#define TMID 2   // T//2
#define ABS2_MASK 0x7FFFFFFF7FFFFFFFULL

__device__ __forceinline__ u64 add2(u64 a, u64 b) {
    u64 d; asm("add.rn.f32x2 %0, %1, %2;" : "=l"(d) : "l"(a), "l"(b)); return d;
}
__device__ __forceinline__ u64 fma2(u64 a, u64 b, u64 c) {
    u64 d; asm("fma.rn.f32x2 %0, %1, %2, %3;" : "=l"(d) : "l"(a), "l"(b), "l"(c)); return d;
}
__device__ __forceinline__ u64 pack2(float v) {
    u64 d; asm("mov.b64 %0, {%1, %1};" : "=l"(d) : "f"(v)); return d;
}
__device__ __forceinline__ float lo2(u64 v) { return __uint_as_float((unsigned)v); }
__device__ __forceinline__ float hi2(u64 v) { return __uint_as_float((unsigned)(v >> 32)); }

// Grid = 128 (64 graphs x 2 halves), 512 threads = 16 warps (4 per SMSP).
// Block owns 32 complete rows i of graph n's 64x64 similarity matrix; the
// column-sum denominator equals the row sum by exact (bitwise) symmetry of S.
// Warp w = (igrp = w>>1, jhalf = w&1): rows igrp*4..+3, j = jhalf*32 + lane.
// Packed pairs: {(i0,j),(i1,j)} and {(i2,j),(i3,j)}; xsN = -x makes the diff
// an add.rn.f32x2; abs via 64-bit sign-mask AND on the alu pipe.
__global__ __launch_bounds__(512, 1)
void gl_kernel(const float* __restrict__ x,
               const float* __restrict__ a,
               float* __restrict__ out) {
    extern __shared__ float sm[];
    float* xsT = sm;                          // [FF][VV]  x transposed,  64 KB
    float* xsN = sm + FF * VV;                // [FF][VV] -x transposed,  64 KB
    u64*   a2s = (u64*)(sm + 2 * FF * VV);    // [FF] packed (a_f, a_f),   2 KB
    float* red = (float*)(a2s + FF);          // [64] row partials,       256 B

    const int b    = blockIdx.x;
    const int n    = b >> 1;
    const int half = b & 1;
    const int tid  = threadIdx.x;
    const int lane = tid & 31;
    const int warp = tid >> 5;

    const float* xm = x + ((size_t)n * TT + TMID) * (size_t)(VV * FF);

    // ---- Stage: xsT[f*VV+v] = xm[v*FF+f], xsN = negated. ----
    // v = idx&63 gives 32 distinct v per warp -> conflict-free STS.
    const float4* x4 = (const float4*)xm;
    #pragma unroll
    for (int idx = tid; idx < VV * (FF / 4); idx += 512) {
        int v  = idx & 63;
        int f4 = idx >> 6;
        float4 val = x4[v * (FF / 4) + f4];
        int f = f4 * 4;
        xsT[(f + 0) * VV + v] =  val.x;  xsN[(f + 0) * VV + v] = -val.x;
        xsT[(f + 1) * VV + v] =  val.y;  xsN[(f + 1) * VV + v] = -val.y;
        xsT[(f + 2) * VV + v] =  val.z;  xsN[(f + 2) * VV + v] = -val.z;
        xsT[(f + 3) * VV + v] =  val.w;  xsN[(f + 3) * VV + v] = -val.w;
    }
    if (tid < FF) a2s[tid] = pack2(a[tid]);
    __syncthreads();

    const int igrp   = warp >> 1;                 // 0..7
    const int jhalf  = warp & 1;
    const int i_loc  = igrp * 4;                  // local row base (0..28)
    const int i_base = half * 32 + i_loc;         // 16B-aligned in xsT rows
    const int j      = jhalf * 32 + lane;         // one j per lane

    const float* pT = xsT + i_base;
    const float* pJ = xsN + j;
    const u64*   pa = a2s;

    u64 acc01 = 0, acc23 = 0;

    // ---- Main loop: per f, LDS.128 + LDS.32 + LDS.64, 4 packed fma-ops ----
    #pragma unroll 8
    for (int f = 0; f < FF; f++) {
        ulonglong2 xi = *(const ulonglong2*)pT;   // (xi0,xi1),(xi2,xi3) bcast
        float njs = *pJ;                          // -xj, 1 wavefront
        u64 av    = pa[f];                        // broadcast
        u64 nj2   = pack2(njs);

        acc01 = fma2(av, add2(xi.x, nj2) & ABS2_MASK, acc01); // rows i0,i1
        acc23 = fma2(av, add2(xi.y, nj2) & ABS2_MASK, acc23); // rows i2,i3

        pT += VV; pJ += VV;
    }

    // ---- exp per element ----
    const float LOG2E = 1.4426950408889634f;
    float s0 = exp2f(lo2(acc01) * LOG2E);   // (i0, j)
    float s1 = exp2f(hi2(acc01) * LOG2E);   // (i1, j)
    float s2 = exp2f(lo2(acc23) * LOG2E);   // (i2, j)
    float s3 = exp2f(hi2(acc23) * LOG2E);   // (i3, j)

    // ---- row partial sums within warp (32 j's), then cross-half combine ----
    float r0 = s0, r1 = s1, r2 = s2, r3 = s3;
    #pragma unroll
    for (int off = 16; off > 0; off >>= 1) {
        r0 += __shfl_xor_sync(0xFFFFFFFFu, r0, off);
        r1 += __shfl_xor_sync(0xFFFFFFFFu, r1, off);
        r2 += __shfl_xor_sync(0xFFFFFFFFu, r2, off);
        r3 += __shfl_xor_sync(0xFFFFFFFFu, r3, off);
    }
    if (lane < 4) {
        float rv = (lane == 0) ? r0 : (lane == 1) ? r1 : (lane == 2) ? r2 : r3;
        red[jhalf * 32 + i_loc + lane] = rv;
    }
    __syncthreads();

    float inv0 = 1.0f / (red[i_loc + 0] + red[32 + i_loc + 0]);
    float inv1 = 1.0f / (red[i_loc + 1] + red[32 + i_loc + 1]);
    float inv2 = 1.0f / (red[i_loc + 2] + red[32 + i_loc + 2]);
    float inv3 = 1.0f / (red[i_loc + 3] + red[32 + i_loc + 3]);

    float* ob = out + ((size_t)(n * VV + i_base)) * VV + j;
    ob[0 * VV] = s0 * inv0;
    ob[1 * VV] = s1 * inv1;
    ob[2 * VV] = s2 * inv2;
    ob[3 * VV] = s3 * inv3;
}

extern "C" void kernel_launch(void* const* d_in, const int* in_sizes, int n_in,
                              void* d_out, int out_size) {
    const float* x = (const float*)d_in[0];   // (64,5,64,256) float32
    const float* a = (const float*)d_in[1];   // (256,1) float32
    float* out = (float*)d_out;               // (64,64,64) float32

    const int smem_bytes = 2 * FF * VV * (int)sizeof(float)
                         + FF * (int)sizeof(u64) + 64 * (int)sizeof(float);
    cudaFuncSetAttribute(gl_kernel, cudaFuncAttributeMaxDynamicSharedMemorySize,
                         smem_bytes);
    gl_kernel<<<NN * 2, 512, smem_bytes>>>(x, a, out);
}

// round 8
// speedup vs baseline: 1.1195x; 1.1195x over previous
#include <cuda_runtime.h>

typedef unsigned long long u64;

#define NN 64
#define TT 5
#define VV 64
#define FF 256
#define TMID 2   // T//2
#define ABS2_MASK 0x7FFFFFFF7FFFFFFFULL

__device__ __forceinline__ u64 add2(u64 a, u64 b) {
    u64 d; asm("add.rn.f32x2 %0, %1, %2;" : "=l"(d) : "l"(a), "l"(b)); return d;
}
__device__ __forceinline__ u64 fma2(u64 a, u64 b, u64 c) {
    u64 d; asm("fma.rn.f32x2 %0, %1, %2, %3;" : "=l"(d) : "l"(a), "l"(b), "l"(c)); return d;
}
__device__ __forceinline__ u64 pack2(float v) {
    u64 d; asm("mov.b64 %0, {%1, %1};" : "=l"(d) : "f"(v)); return d;
}
__device__ __forceinline__ u64 swap2(u64 v) {
    u64 d;
    asm("{.reg .b32 lo, hi; mov.b64 {lo, hi}, %1; mov.b64 %0, {hi, lo};}"
        : "=l"(d) : "l"(v));
    return d;
}
__device__ __forceinline__ float lo2(u64 v) { return __uint_as_float((unsigned)v); }
__device__ __forceinline__ float hi2(u64 v) { return __uint_as_float((unsigned)(v >> 32)); }

// Grid = 128 (64 graphs x 2 halves), 512 threads = 16 warps (4 per SMSP).
// Block owns 32 complete rows i of graph n's 64x64 similarity matrix; the
// column-sum denominator equals the row sum by exact (bitwise) symmetry of S.
//
// Tile shape is identical to the R5 winner (warp-tile = 4 rows x 64 j,
// diagonal f32x2 packing, no operand splat), but the f-dimension is SPLIT:
// warp w and warp w+8 compute the same tile over f in [0,128) / [128,256).
// Same total instruction count as R5, twice the warps per SMSP for latency
// hiding. Partial accumulators merge via one packed add through smem.
__global__ __launch_bounds__(512, 1)
void gl_kernel(const float* __restrict__ x,
               const float* __restrict__ a,
               float* __restrict__ out) {
    extern __shared__ float sm[];
    float* xsT = sm;                          // [FF][VV]  x transposed,  64 KB
    float* xsN = sm + FF * VV;                // [FF][VV] -x transposed,  64 KB
    u64*   a2s = (u64*)(sm + 2 * FF * VV);    // [FF] packed (a_f, a_f),   2 KB
    u64*   ex  = a2s + FF;                    // [4][8][32] f-half partials, 8 KB

    const int b    = blockIdx.x;
    const int n    = b >> 1;
    const int half = b & 1;
    const int tid  = threadIdx.x;
    const int lane = tid & 31;
    const int warp = tid >> 5;

    const float* xm = x + ((size_t)n * TT + TMID) * (size_t)(VV * FF);

    // ---- Stage: xsT[f*VV+v] = xm[v*FF+f], xsN = negated. ----
    // v = idx&63 gives 32 distinct v per warp -> conflict-free STS.
    const float4* x4 = (const float4*)xm;
    #pragma unroll
    for (int idx = tid; idx < VV * (FF / 4); idx += 512) {
        int v  = idx & 63;
        int f4 = idx >> 6;
        float4 val = x4[v * (FF / 4) + f4];
        int f = f4 * 4;
        xsT[(f + 0) * VV + v] =  val.x;  xsN[(f + 0) * VV + v] = -val.x;
        xsT[(f + 1) * VV + v] =  val.y;  xsN[(f + 1) * VV + v] = -val.y;
        xsT[(f + 2) * VV + v] =  val.z;  xsN[(f + 2) * VV + v] = -val.z;
        xsT[(f + 3) * VV + v] =  val.w;  xsN[(f + 3) * VV + v] = -val.w;
    }
    if (tid < FF) a2s[tid] = pack2(a[tid]);
    __syncthreads();

    const int igrp   = warp & 7;                // tile id: rows igrp*4..+3
    const int fhalf  = warp >> 3;               // 0 or 1: f-range half
    const int i_base = half * 32 + igrp * 4;    // 16B-aligned in xsT rows
    const int j0     = lane << 1;

    const int fofs = fhalf * (FF / 2);
    const float* pT = xsT + fofs * VV + i_base;
    const float* pN = xsN + fofs * VV + j0;
    const u64*   pa = a2s + fofs;

    u64 acc1 = 0, acc2 = 0, acc3 = 0, acc4 = 0;

    // ---- Main loop: 128 f per warp; 1 LDS.128 + 2 LDS.64, 8 packed ops ----
    #pragma unroll 8
    for (int f = 0; f < FF / 2; f++) {
        ulonglong2 xi = *(const ulonglong2*)pT;   // (xi0,xi1),(xi2,xi3) bcast
        u64 nj  = *(const u64*)pN;                // (-xj0,-xj1)
        u64 av  = pa[f];
        u64 njr = swap2(nj);                      // (-xj1,-xj0)

        acc1 = fma2(av, add2(xi.x, nj ) & ABS2_MASK, acc1); // (i0,j0)(i1,j1)
        acc2 = fma2(av, add2(xi.x, njr) & ABS2_MASK, acc2); // (i0,j1)(i1,j0)
        acc3 = fma2(av, add2(xi.y, nj ) & ABS2_MASK, acc3); // (i2,j0)(i3,j1)
        acc4 = fma2(av, add2(xi.y, njr) & ABS2_MASK, acc4); // (i2,j1)(i3,j0)

        pT += VV; pN += VV;
    }

    // ---- Merge f-halves: warp w+8 publishes, warp w adds. ----
    // Layout ex[k*256 + igrp*32 + lane]: 8B stride across lanes.
    if (fhalf) {
        u64* p = ex + igrp * 32 + lane;
        p[0]   = acc1;  p[256] = acc2;  p[512] = acc3;  p[768] = acc4;
    }
    __syncthreads();
    if (fhalf) return;

    {
        const u64* p = ex + igrp * 32 + lane;
        acc1 = add2(acc1, p[0]);
        acc2 = add2(acc2, p[256]);
        acc3 = add2(acc3, p[512]);
        acc4 = add2(acc4, p[768]);
    }

    // ---- exp, per-row warp reduction (row sum == reference column sum) ----
    const float LOG2E = 1.4426950408889634f;
    float s_i0j0 = exp2f(lo2(acc1) * LOG2E);
    float s_i1j1 = exp2f(hi2(acc1) * LOG2E);
    float s_i0j1 = exp2f(lo2(acc2) * LOG2E);
    float s_i1j0 = exp2f(hi2(acc2) * LOG2E);
    float s_i2j0 = exp2f(lo2(acc3) * LOG2E);
    float s_i3j1 = exp2f(hi2(acc3) * LOG2E);
    float s_i2j1 = exp2f(lo2(acc4) * LOG2E);
    float s_i3j0 = exp2f(hi2(acc4) * LOG2E);

    float p0 = s_i0j0 + s_i0j1;
    float p1 = s_i1j0 + s_i1j1;
    float p2 = s_i2j0 + s_i2j1;
    float p3 = s_i3j0 + s_i3j1;
    #pragma unroll
    for (int off = 16; off > 0; off >>= 1) {
        p0 += __shfl_xor_sync(0xFFFFFFFFu, p0, off);
        p1 += __shfl_xor_sync(0xFFFFFFFFu, p1, off);
        p2 += __shfl_xor_sync(0xFFFFFFFFu, p2, off);
        p3 += __shfl_xor_sync(0xFFFFFFFFu, p3, off);
    }
    float inv0 = 1.0f / p0, inv1 = 1.0f / p1, inv2 = 1.0f / p2, inv3 = 1.0f / p3;

    float* ob = out + ((size_t)(n * VV + i_base)) * VV + j0;
    *(float2*)(ob + 0 * VV) = make_float2(s_i0j0 * inv0, s_i0j1 * inv0);
    *(float2*)(ob + 1 * VV) = make_float2(s_i1j0 * inv1, s_i1j1 * inv1);
    *(float2*)(ob + 2 * VV) = make_float2(s_i2j0 * inv2, s_i2j1 * inv2);
    *(float2*)(ob + 3 * VV) = make_float2(s_i3j0 * inv3, s_i3j1 * inv3);
}

extern "C" void kernel_launch(void* const* d_in, const int* in_sizes, int n_in,
                              void* d_out, int out_size) {
    const float* x = (const float*)d_in[0];   // (64,5,64,256) float32
    const float* a = (const float*)d_in[1];   // (256,1) float32
    float* out = (float*)d_out;               // (64,64,64) float32

    const int smem_bytes = 2 * FF * VV * (int)sizeof(float)
                         + FF * (int)sizeof(u64)
                         + 4 * 256 * (int)sizeof(u64);
    cudaFuncSetAttribute(gl_kernel, cudaFuncAttributeMaxDynamicSharedMemorySize,
                         smem_bytes);
    gl_kernel<<<NN * 2, 512, smem_bytes>>>(x, a, out);
}

// round 9
// speedup vs baseline: 1.2716x; 1.1358x over previous
#include <cuda_runtime.h>

typedef unsigned long long u64;

#define NN 64
#define TT 5
#define VV 64
#define FF 256
#define TMID 2   // T//2
#define ABS2_MASK 0x7FFFFFFF7FFFFFFFULL

__device__ __forceinline__ u64 add2(u64 a, u64 b) {
    u64 d; asm("add.rn.f32x2 %0, %1, %2;" : "=l"(d) : "l"(a), "l"(b)); return d;
}
__device__ __forceinline__ u64 swap2(u64 v) {
    u64 d;
    asm("{.reg .b32 lo, hi; mov.b64 {lo, hi}, %1; mov.b64 %0, {hi, lo};}"
        : "=l"(d) : "l"(v));
    return d;
}
__device__ __forceinline__ float lo2(u64 v) { return __uint_as_float((unsigned)v); }
__device__ __forceinline__ float hi2(u64 v) { return __uint_as_float((unsigned)(v >> 32)); }

// Grid = 128 (64 graphs x 2 halves), 512 threads = 16 warps.
// Key algebraic move: a_f >= 0, so a_f*|x_i - x_j| == |a_f*x_i - a_f*x_j|.
// We stage y = a .* x (and -y), removing the per-f 'a' load and turning every
// fma-pipe op into a 2-source packed add.
//
// Block owns 32 complete rows i of graph n's 64x64 similarity matrix; the
// column-sum denominator equals the row sum by exact (bitwise) symmetry of S.
// Warp = (tile = w&3 -> rows tile*8..+7, fq = w>>2 -> f in [fq*64, fq*64+64)).
// Lane owns j = 2*lane, 2*lane+1; diagonal f32x2 packing, 8 accumulators.
// f-quarters merge via packed adds through smem; fq==0 warps do the epilogue.
__global__ __launch_bounds__(512, 1)
void gl_kernel(const float* __restrict__ x,
               const float* __restrict__ a,
               float* __restrict__ out) {
    extern __shared__ float sm[];
    float* xsT = sm;                          // [FF][VV]  y = a.*x (transposed)
    float* xsN = sm + FF * VV;                // [FF][VV] -y
    float* a_s = sm + 2 * FF * VV;            // [FF]
    u64*   ex  = (u64*)(a_s + FF);            // [8][3][4][32] partials, 24 KB

    const int b    = blockIdx.x;
    const int n    = b >> 1;
    const int half = b & 1;
    const int tid  = threadIdx.x;
    const int lane = tid & 31;
    const int warp = tid >> 5;

    const float* xm = x + ((size_t)n * TT + TMID) * (size_t)(VV * FF);

    if (tid < FF) a_s[tid] = a[tid];
    __syncthreads();

    // ---- Stage: xsT[f*VV+v] = a[f]*xm[v*FF+f], xsN = negated. ----
    // v = idx&63 gives 32 distinct v per warp -> conflict-free STS.
    const float4* x4 = (const float4*)xm;
    #pragma unroll
    for (int idx = tid; idx < VV * (FF / 4); idx += 512) {
        int v  = idx & 63;
        int f4 = idx >> 6;
        float4 val = x4[v * (FF / 4) + f4];
        int f = f4 * 4;
        float y0 = a_s[f + 0] * val.x;
        float y1 = a_s[f + 1] * val.y;
        float y2 = a_s[f + 2] * val.z;
        float y3 = a_s[f + 3] * val.w;
        xsT[(f + 0) * VV + v] =  y0;  xsN[(f + 0) * VV + v] = -y0;
        xsT[(f + 1) * VV + v] =  y1;  xsN[(f + 1) * VV + v] = -y1;
        xsT[(f + 2) * VV + v] =  y2;  xsN[(f + 2) * VV + v] = -y2;
        xsT[(f + 3) * VV + v] =  y3;  xsN[(f + 3) * VV + v] = -y3;
    }
    __syncthreads();

    const int tile   = warp & 3;                // rows tile*8 .. tile*8+7
    const int fq     = warp >> 2;               // f-quarter 0..3
    const int i_base = half * 32 + tile * 8;    // 32B-aligned in xsT rows
    const int j0     = lane << 1;

    const float* pT = xsT + (fq * (FF / 4)) * VV + i_base;
    const float* pN = xsN + (fq * (FF / 4)) * VV + j0;

    u64 acc[8];
    #pragma unroll
    for (int k = 0; k < 8; k++) acc[k] = 0;

    // ---- Main loop: 64 f per warp; 2 LDS.128 + 1 LDS.64, 24 packed ops,
    //      covering 512 pair-f per iteration. ----
    #pragma unroll 4
    for (int f = 0; f < FF / 4; f++) {
        ulonglong2 xiA = *(const ulonglong2*)pT;        // (y_i0,y_i1),(y_i2,y_i3)
        ulonglong2 xiB = *(const ulonglong2*)(pT + 4);  // (y_i4,y_i5),(y_i6,y_i7)
        u64 nj  = *(const u64*)pN;                      // (-y_j0,-y_j1)
        u64 njr = swap2(nj);                            // (-y_j1,-y_j0)

        acc[0] = add2(acc[0], add2(xiA.x, nj ) & ABS2_MASK); // (i0,j0)(i1,j1)
        acc[1] = add2(acc[1], add2(xiA.x, njr) & ABS2_MASK); // (i0,j1)(i1,j0)
        acc[2] = add2(acc[2], add2(xiA.y, nj ) & ABS2_MASK); // (i2,j0)(i3,j1)
        acc[3] = add2(acc[3], add2(xiA.y, njr) & ABS2_MASK); // (i2,j1)(i3,j0)
        acc[4] = add2(acc[4], add2(xiB.x, nj ) & ABS2_MASK); // (i4,j0)(i5,j1)
        acc[5] = add2(acc[5], add2(xiB.x, njr) & ABS2_MASK); // (i4,j1)(i5,j0)
        acc[6] = add2(acc[6], add2(xiB.y, nj ) & ABS2_MASK); // (i6,j0)(i7,j1)
        acc[7] = add2(acc[7], add2(xiB.y, njr) & ABS2_MASK); // (i6,j1)(i7,j0)

        pT += VV; pN += VV;
    }

    // ---- Merge f-quarters: fq>0 publish, fq==0 adds. ----
    // ex index: k*384 + (fq-1)*128 + tile*32 + lane  (8B lane stride: no conflicts)
    if (fq) {
        u64* p = ex + (fq - 1) * 128 + tile * 32 + lane;
        #pragma unroll
        for (int k = 0; k < 8; k++) p[k * 384] = acc[k];
    }
    __syncthreads();
    if (fq) return;

    {
        const u64* p = ex + tile * 32 + lane;
        #pragma unroll
        for (int k = 0; k < 8; k++) {
            u64 s01 = add2(p[k * 384], p[k * 384 + 128]);
            acc[k]  = add2(add2(acc[k], p[k * 384 + 256]), s01);
        }
    }

    // ---- exp, per-row warp reduction (row sum == reference column sum) ----
    const float LOG2E = 1.4426950408889634f;
    float sl[8], sh[8];
    #pragma unroll
    for (int k = 0; k < 8; k++) {
        sl[k] = exp2f(lo2(acc[k]) * LOG2E);
        sh[k] = exp2f(hi2(acc[k]) * LOG2E);
    }
    // row 2r  : j0 -> sl[2r],   j1 -> sl[2r+1]
    // row 2r+1: j0 -> sh[2r+1], j1 -> sh[2r]
    float p[8];
    #pragma unroll
    for (int r = 0; r < 4; r++) {
        p[2 * r]     = sl[2 * r] + sl[2 * r + 1];
        p[2 * r + 1] = sh[2 * r] + sh[2 * r + 1];
    }
    #pragma unroll
    for (int off = 16; off > 0; off >>= 1) {
        #pragma unroll
        for (int r = 0; r < 8; r++)
            p[r] += __shfl_xor_sync(0xFFFFFFFFu, p[r], off);
    }

    float* ob = out + ((size_t)(n * VV + i_base)) * VV + j0;
    #pragma unroll
    for (int r = 0; r < 4; r++) {
        float inv0 = 1.0f / p[2 * r];
        float inv1 = 1.0f / p[2 * r + 1];
        *(float2*)(ob + (2 * r)     * VV) =
            make_float2(sl[2 * r] * inv0, sl[2 * r + 1] * inv0);
        *(float2*)(ob + (2 * r + 1) * VV) =
            make_float2(sh[2 * r + 1] * inv1, sh[2 * r] * inv1);
    }
}

extern "C" void kernel_launch(void* const* d_in, const int* in_sizes, int n_in,
                              void* d_out, int out_size) {
    const float* x = (const float*)d_in[0];   // (64,5,64,256) float32
    const float* a = (const float*)d_in[1];   // (256,1) float32
    float* out = (float*)d_out;               // (64,64,64) float32

    const int smem_bytes = 2 * FF * VV * (int)sizeof(float)   // xsT + xsN
                         + FF * (int)sizeof(float)            // a_s
                         + 8 * 384 * (int)sizeof(u64);        // ex (24 KB)
    cudaFuncSetAttribute(gl_kernel, cudaFuncAttributeMaxDynamicSharedMemorySize,
                         smem_bytes);
    gl_kernel<<<NN * 2, 512, smem_bytes>>>(x, a, out);
}